// round 1
// baseline (speedup 1.0000x reference)
#include <cuda_runtime.h>
#include <cuda_bf16.h>
#include <cstdint>

// Problem constants
#define BATCH   32
#define IN_F    8192
#define OUT_F   8192

#define KSPLIT  16          // K splits
#define KCHUNK  (IN_F / KSPLIT)   // 512 k per CTA
#define SUBK    256         // k sub-chunk staged in SMEM (32 KB)
#define TILE_N  512         // columns per CTA
#define NTILES  (OUT_F / TILE_N)  // 16

// Device scratch (allowed: __device__ globals, no runtime allocation)
__device__ float g_xT[IN_F * BATCH];                  // 1 MB: xT[k][b]
__device__ float g_part[KSPLIT * BATCH * OUT_F];      // 16 MB: part[ks][b][o]

// ---------------- f32x2 helpers (sm_100+ packed fp32) ----------------
__device__ __forceinline__ unsigned long long ffma2(unsigned long long a,
                                                    unsigned long long b,
                                                    unsigned long long c) {
    unsigned long long d;
    asm("fma.rn.f32x2 %0, %1, %2, %3;" : "=l"(d) : "l"(a), "l"(b), "l"(c));
    return d;
}
__device__ __forceinline__ unsigned long long pack_dup(float v) {
    unsigned long long u;
    asm("mov.b64 %0, {%1, %2};" : "=l"(u) : "f"(v), "f"(v));
    return u;
}
__device__ __forceinline__ float2 unpack2(unsigned long long u) {
    float2 f;
    asm("mov.b64 {%0, %1}, %2;" : "=f"(f.x), "=f"(f.y) : "l"(u));
    return f;
}

// ---------------- kernel 1: transpose x [32, 8192] -> xT [8192, 32] --------
// 65536 threads: t = k*8 + bg; each handles 4 batches for one k.
__global__ void transpose_x_kernel(const float* __restrict__ x) {
    int t  = blockIdx.x * blockDim.x + threadIdx.x;   // 0..65535
    int k  = t >> 3;
    int bg = t & 7;                                   // batch group of 4
    float4 v;
    v.x = x[(size_t)(bg * 4 + 0) * IN_F + k];
    v.y = x[(size_t)(bg * 4 + 1) * IN_F + k];
    v.z = x[(size_t)(bg * 4 + 2) * IN_F + k];
    v.w = x[(size_t)(bg * 4 + 3) * IN_F + k];
    *reinterpret_cast<float4*>(&g_xT[(size_t)k * BATCH + bg * 4]) = v;
}

// ---------------- kernel 2: partial GEMM ----------------
// Grid: 256 CTAs = 16 N-tiles x 16 K-splits, blockDim 256.
// Each thread: 2 consecutive output columns, 32 batch accumulators
// as 16 f32x2 pairs per column.
__global__ void gemv_partial_kernel(const int* __restrict__ W) {
    __shared__ float xs[SUBK][BATCH];   // 32 KB

    const int nb = blockIdx.x & (NTILES - 1);
    const int kb = blockIdx.x >> 4;     // 16 ntiles -> shift 4
    const int col = nb * TILE_N + threadIdx.x * 2;

    unsigned long long acc0[16], acc1[16];
#pragma unroll
    for (int i = 0; i < 16; ++i) { acc0[i] = 0ULL; acc1[i] = 0ULL; }

    const int k_base = kb * KCHUNK;

    for (int sc = 0; sc < KCHUNK / SUBK; ++sc) {
        const int ks0 = k_base + sc * SUBK;

        // cooperative fill of xs from xT (contiguous copy)
        {
            const float4* src = reinterpret_cast<const float4*>(&g_xT[(size_t)ks0 * BATCH]);
            float4* dst = reinterpret_cast<float4*>(&xs[0][0]);
#pragma unroll
            for (int i = threadIdx.x; i < SUBK * BATCH / 4; i += 256)
                dst[i] = src[i];
        }
        __syncthreads();

        const int2* Wp = reinterpret_cast<const int2*>(W + (size_t)ks0 * OUT_F + col);

#pragma unroll 4
        for (int kk = 0; kk < SUBK; ++kk) {
            int2 w = Wp[(size_t)kk * (OUT_F / 2)];
            float w0 = (float)w.x;
            float w1 = (float)w.y;
            unsigned long long w0p = pack_dup(w0);
            unsigned long long w1p = pack_dup(w1);

            const ulonglong2* xr = reinterpret_cast<const ulonglong2*>(&xs[kk][0]);
#pragma unroll
            for (int q = 0; q < 8; ++q) {
                ulonglong2 xv = xr[q];            // LDS.128: batches 4q..4q+3
                acc0[2 * q]     = ffma2(xv.x, w0p, acc0[2 * q]);
                acc1[2 * q]     = ffma2(xv.x, w1p, acc1[2 * q]);
                acc0[2 * q + 1] = ffma2(xv.y, w0p, acc0[2 * q + 1]);
                acc1[2 * q + 1] = ffma2(xv.y, w1p, acc1[2 * q + 1]);
            }
        }
        __syncthreads();
    }

    // write partials: part[kb][b][col..col+1], coalesced float2 stores
    float* dst = g_part + (size_t)kb * BATCH * OUT_F + col;
#pragma unroll
    for (int bp = 0; bp < 16; ++bp) {
        float2 a0 = unpack2(acc0[bp]);   // (b=2bp, b=2bp+1) for col
        float2 a1 = unpack2(acc1[bp]);   // same batches for col+1
        float2 r0 = make_float2(a0.x, a1.x);
        float2 r1 = make_float2(a0.y, a1.y);
        *reinterpret_cast<float2*>(dst + (size_t)(2 * bp)     * OUT_F) = r0;
        *reinterpret_cast<float2*>(dst + (size_t)(2 * bp + 1) * OUT_F) = r1;
    }
}

// ---------------- kernel 3: reduce K-splits + apply scaler ----------------
__global__ void reduce_kernel(const float* __restrict__ scaler, float* __restrict__ out) {
    const int i = blockIdx.x * blockDim.x + threadIdx.x;  // over 65536 float4
    const float4* p = reinterpret_cast<const float4*>(g_part);
    float4 s = p[i];
#pragma unroll
    for (int ks = 1; ks < KSPLIT; ++ks) {
        float4 v = p[(size_t)ks * (BATCH * OUT_F / 4) + i];
        s.x += v.x; s.y += v.y; s.z += v.z; s.w += v.w;
    }
    const float sc = scaler[0];
    s.x *= sc; s.y *= sc; s.z *= sc; s.w *= sc;
    reinterpret_cast<float4*>(out)[i] = s;
}

extern "C" void kernel_launch(void* const* d_in, const int* in_sizes, int n_in,
                              void* d_out, int out_size) {
    const float* x      = (const float*)d_in[0];   // [32, 8192] fp32
    const int*   W      = (const int*)d_in[1];     // [8192, 8192] int32 (int8-valued)
    const float* scaler = (const float*)d_in[2];   // [1] fp32
    float* out = (float*)d_out;                    // [32, 8192] fp32

    transpose_x_kernel<<<256, 256>>>(x);
    gemv_partial_kernel<<<NTILES * KSPLIT, 256>>>(W);
    reduce_kernel<<<BATCH * OUT_F / 4 / 256, 256>>>(scaler, out);
}

// round 13
// speedup vs baseline: 1.1582x; 1.1582x over previous
#include <cuda_runtime.h>
#include <cuda_bf16.h>
#include <cstdint>

// ---------------- Problem constants ----------------
#define BATCH   32
#define IN_F    8192
#define OUT_F   8192

#define TILE_N   64                 // output columns per CTA
#define NB_CTAS  (OUT_F / TILE_N)   // 128 CTAs, single wave
#define CHUNK_K  64
#define NCHUNKS  (IN_F / CHUNK_K)   // 128

// A image: per chunk, [m=64][k=64] bf16 with XOR-granule swizzle, 8KB.
// rows 0-31 = bf16(x), rows 32-63 = bf16 residual (lo part).
__device__ __align__(16) unsigned char g_A[NCHUNKS * 8192];   // 1 MB

// ---------------- helpers ----------------
__device__ __forceinline__ uint32_t smem_u32(const void* p) {
    uint32_t a;
    asm("{ .reg .u64 t; cvta.to.shared.u64 t, %1; cvt.u32.u64 %0, t; }"
        : "=r"(a) : "l"(p));
    return a;
}
// pack two fp32 -> bf16x2 (lo -> lower half, hi -> upper half), round-to-nearest
__device__ __forceinline__ uint32_t cvt2bf(float lo, float hi) {
    uint32_t r;
    asm("cvt.rn.satfinite.bf16x2.f32 %0, %1, %2;" : "=r"(r) : "f"(hi), "f"(lo));
    return r;
}
__device__ __forceinline__ void ldsm4(uint32_t* r, uint32_t a) {
    asm volatile("ldmatrix.sync.aligned.m8n8.x4.shared.b16 {%0,%1,%2,%3}, [%4];"
                 : "=r"(r[0]), "=r"(r[1]), "=r"(r[2]), "=r"(r[3]) : "r"(a));
}
__device__ __forceinline__ void ldsm4t(uint32_t* r, uint32_t a) {
    asm volatile("ldmatrix.sync.aligned.m8n8.x4.trans.shared.b16 {%0,%1,%2,%3}, [%4];"
                 : "=r"(r[0]), "=r"(r[1]), "=r"(r[2]), "=r"(r[3]) : "r"(a));
}
__device__ __forceinline__ void mma16816(float* d, const uint32_t* a,
                                         uint32_t b0, uint32_t b1) {
    asm volatile(
        "mma.sync.aligned.m16n8k16.row.col.f32.bf16.bf16.f32 "
        "{%0,%1,%2,%3}, {%4,%5,%6,%7}, {%8,%9}, {%0,%1,%2,%3};"
        : "+f"(d[0]), "+f"(d[1]), "+f"(d[2]), "+f"(d[3])
        : "r"(a[0]), "r"(a[1]), "r"(a[2]), "r"(a[3]), "r"(b0), "r"(b1));
}

// ---------------- kernel 1: build swizzled A images (hi/lo split of x) ----
// addr(c,m,k) = c*8192 + m*128 + 16*((k>>3)^(m&7)) + (k&7)*2
__global__ void prep_A_kernel(const float* __restrict__ x) {
    const int c = blockIdx.x;
    const int tid = threadIdx.x;
    const int m = tid >> 2;          // 0..63
    const int kq = tid & 3;          // 16-k group
    const int b = m & 31;
    const bool lo = (m >= 32);

    const float* xp = x + (size_t)b * IN_F + c * CHUNK_K + kq * 16;
    float v[16];
#pragma unroll
    for (int j = 0; j < 4; ++j) {
        float4 t = reinterpret_cast<const float4*>(xp)[j];
        v[4 * j] = t.x; v[4 * j + 1] = t.y; v[4 * j + 2] = t.z; v[4 * j + 3] = t.w;
    }
    if (lo) {
#pragma unroll
        for (int i = 0; i < 16; ++i)
            v[i] = v[i] - __bfloat162float(__float2bfloat16(v[i]));
    }
    uint32_t p[8];
#pragma unroll
    for (int i = 0; i < 8; ++i) p[i] = cvt2bf(v[2 * i], v[2 * i + 1]);

    unsigned char* base = g_A + (size_t)c * 8192 + m * 128;
#pragma unroll
    for (int g = 0; g < 2; ++g) {
        int k0 = kq * 16 + g * 8;
        uint32_t gran = (uint32_t)((k0 >> 3) ^ (m & 7));
        *reinterpret_cast<uint4*>(base + gran * 16) =
            make_uint4(p[4 * g], p[4 * g + 1], p[4 * g + 2], p[4 * g + 3]);
    }
}

// ---------------- kernel 2: dequant + mma.sync GEMM ----------------
__global__ __launch_bounds__(256, 1) void gemm_kernel(const int* __restrict__ W,
                                                      const float* __restrict__ scaler,
                                                      float* __restrict__ out) {
    __shared__ __align__(16) unsigned char sW[2][8192];   // [k=64][n=64] bf16, swizzled
    __shared__ __align__(16) unsigned char sA[2][8192];   // [m=64][k=64] bf16, swizzled

    const int tid = threadIdx.x;
    const int nb = blockIdx.x;
    const int lane = tid & 31;
    const int wid = tid >> 5;
    const int wm = wid >> 2;       // 0..1 : m-half
    const int wn = wid & 3;        // 0..3 : n16 group
    const int kr = tid >> 2;       // W load row (0..63)
    const int ng = tid & 3;        // W load n-subgroup

    const uint32_t swb = smem_u32(sW);
    const uint32_t sab = smem_u32(sA);

    // per-lane ldmatrix offsets (constant over chunks)
    uint32_t offA[2][4], offB[4];
    {
        const int lm = (lane & 7) + 8 * ((lane >> 3) & 1);
        const int kh = lane >> 4;
#pragma unroll
        for (int T = 0; T < 2; ++T) {
            int mm = 16 * wm + 32 * T + lm;   // tile wm (hi) / wm+2 (lo)
#pragma unroll
            for (int s = 0; s < 4; ++s)
                offA[T][s] = (uint32_t)(mm * 128 + (((2 * s + kh) ^ (mm & 7)) << 4));
        }
        const int kkb = (lane & 7) + 8 * ((lane >> 3) & 1);
        const int gr = 2 * wn + (lane >> 4);
#pragma unroll
        for (int s = 0; s < 4; ++s) {
            int kk = 16 * s + kkb;
            offB[s] = (uint32_t)(kk * 128 + ((gr ^ (kk & 7)) << 4));
        }
    }

    float acc[2][2][4];
#pragma unroll
    for (int t = 0; t < 2; ++t)
#pragma unroll
        for (int f = 0; f < 2; ++f)
#pragma unroll
            for (int i = 0; i < 4; ++i) acc[t][f][i] = 0.0f;

    int4 wr[4];
    uint4 ar[2];

#define LOADW(c) do {                                                          \
    const int4* bp = reinterpret_cast<const int4*>(                            \
        W + (size_t)(CHUNK_K * (c) + kr) * OUT_F + TILE_N * nb);               \
    wr[0] = bp[ng];  wr[1] = bp[4 + ng];                                       \
    wr[2] = bp[8 + ng]; wr[3] = bp[12 + ng];                                   \
} while (0)
#define LOADA(c) do {                                                          \
    const uint4* ap = reinterpret_cast<const uint4*>(g_A + (size_t)(c) * 8192);\
    ar[0] = ap[tid]; ar[1] = ap[tid + 256];                                    \
} while (0)
#define STORE(buf) do {                                                        \
    _Pragma("unroll")                                                          \
    for (int j = 0; j < 4; ++j) {                                              \
        int n_local = 16 * j + 4 * ng;                                         \
        uint32_t q0 = cvt2bf((float)wr[j].x, (float)wr[j].y);                  \
        uint32_t q1 = cvt2bf((float)wr[j].z, (float)wr[j].w);                  \
        unsigned char* p = sW[buf] + kr * 128 +                                \
            (((n_local >> 3) ^ (kr & 7)) << 4) + (n_local & 7) * 2;            \
        *reinterpret_cast<uint2*>(p) = make_uint2(q0, q1);                     \
    }                                                                          \
    reinterpret_cast<uint4*>(sA[buf])[tid] = ar[0];                            \
    reinterpret_cast<uint4*>(sA[buf])[tid + 256] = ar[1];                      \
} while (0)

    LOADW(0); LOADA(0); STORE(0);
    __syncthreads();

    for (int c = 0; c < NCHUNKS; ++c) {
        const int buf = c & 1;
        if (c + 1 < NCHUNKS) { LOADW(c + 1); LOADA(c + 1); }

        const uint32_t ab = sab + (uint32_t)buf * 8192u;
        const uint32_t wb = swb + (uint32_t)buf * 8192u;
#pragma unroll
        for (int s = 0; s < 4; ++s) {
            uint32_t a0[4], a1[4], b[4];
            ldsm4(a0, ab + offA[0][s]);
            ldsm4(a1, ab + offA[1][s]);
            ldsm4t(b, wb + offB[s]);
            mma16816(acc[0][0], a0, b[0], b[1]);
            mma16816(acc[0][1], a0, b[2], b[3]);
            mma16816(acc[1][0], a1, b[0], b[1]);
            mma16816(acc[1][1], a1, b[2], b[3]);
        }
        __syncthreads();
        if (c + 1 < NCHUNKS) { STORE(buf ^ 1); __syncthreads(); }
    }

    // epilogue: (hi + lo) * scaler, coalesced float2 stores
    const float sc = scaler[0];
    const int row0 = 16 * wm + (lane >> 2);
    const int ncol = TILE_N * nb + 16 * wn + 2 * (lane & 3);
#pragma unroll
    for (int f = 0; f < 2; ++f) {
        float2 r0 = make_float2((acc[0][f][0] + acc[1][f][0]) * sc,
                                (acc[0][f][1] + acc[1][f][1]) * sc);
        float2 r1 = make_float2((acc[0][f][2] + acc[1][f][2]) * sc,
                                (acc[0][f][3] + acc[1][f][3]) * sc);
        *reinterpret_cast<float2*>(out + (size_t)row0 * OUT_F + ncol + 8 * f) = r0;
        *reinterpret_cast<float2*>(out + (size_t)(row0 + 8) * OUT_F + ncol + 8 * f) = r1;
    }
#undef LOADW
#undef LOADA
#undef STORE
}

extern "C" void kernel_launch(void* const* d_in, const int* in_sizes, int n_in,
                              void* d_out, int out_size) {
    const float* x      = (const float*)d_in[0];   // [32, 8192] fp32
    const int*   W      = (const int*)d_in[1];     // [8192, 8192] int32 (int8-valued)
    const float* scaler = (const float*)d_in[2];   // [1] fp32
    float* out = (float*)d_out;                    // [32, 8192] fp32

    prep_A_kernel<<<NCHUNKS, 256>>>(x);
    gemm_kernel<<<NB_CTAS, 256>>>(W, scaler, out);
}